// round 11
// baseline (speedup 1.0000x reference)
#include <cuda_runtime.h>
#include <cuda_bf16.h>
#include <cstdint>

// Problem dims
#define B_    256
#define T_    1000
#define F_    64
#define H1_   256
#define H2_   128
#define NCLS_ 5
#define DMLP_ 128

// Persistent-kernel config: 8 groups x 16 CTAs = 128 CTAs co-resident
#define NG    8
#define CPG   16
#define NB    32
#define NTH   512

// MMA tiling
#define NK1   40          // L1 k-steps (K=320, 8 per step)
#define NK2   48          // L2 k-steps (K=384)

// SMEM layout (float offsets)
#define SACT_S   452      // [batch][x(64) | h1(256) | h2(128)] stride, ≡4 mod 32
#define SRED_S   34
#define OFF_WA1  0                        // 4*NK1*32*4  = 20480
#define OFF_WA2  (OFF_WA1 + 20480)        // 2*NK2*32*4  = 12288
#define OFF_ACT  (OFF_WA2 + 12288)        // 32*452      = 14464
#define OFF_RED1 (OFF_ACT + 14464)        // 2 copies *64*34 = 4352
#define OFF_RED2 (OFF_RED1 + 4352)        // 4 copies *32*34 = 4352
#define OFF_B1   (OFF_RED2 + 4352)        // 64
#define OFF_B2   (OFF_B1 + 64)            // 32
#define OFF_C1   (OFF_B2 + 32)            // 512
#define OFF_C2   (OFF_C1 + 512)           // 256
#define SMEM_FLOATS (OFF_C2 + 256)
#define SMEM_BYTES  (SMEM_FLOATS * 4)     // 227200 B

typedef unsigned long long u64t;

// Ping-pong state buffers: h(s) lives in buf[s&1]. Writer of h(t+1) and reader
// of h(t) can never touch the same buffer -> WAR race across CTAs eliminated.
__device__ float    g_h1[2][B_ * H1_];
__device__ float    g_h2[2][B_ * H2_];
__device__ unsigned g_cnt[NG];
__device__ unsigned g_done[NG];

__device__ __forceinline__ unsigned f2tf(float f) {
    unsigned u;
    asm("cvt.rna.tf32.f32 %0, %1;" : "=r"(u) : "f"(f));
    return u;
}
__device__ __forceinline__ void mma8(float* d, uint4 a, unsigned b0, unsigned b1) {
    asm("mma.sync.aligned.m16n8k8.row.col.f32.tf32.tf32.f32 "
        "{%0,%1,%2,%3},{%4,%5,%6,%7},{%8,%9},{%0,%1,%2,%3};"
        : "+f"(d[0]), "+f"(d[1]), "+f"(d[2]), "+f"(d[3])
        : "r"(a.x), "r"(a.y), "r"(a.z), "r"(a.w), "r"(b0), "r"(b1));
}
__device__ __forceinline__ float tanhfast(float x) {
    float y;
    asm("tanh.approx.f32 %0, %1;" : "=f"(y) : "f"(x));
    return y;
}
__device__ __forceinline__ float sigm(float x)  { return 0.5f * tanhfast(0.5f * x) + 0.5f; }

extern __shared__ float smem[];

__global__ void __launch_bounds__(NTH, 1) lstm_persistent(
    const float* __restrict__ x,
    const float* __restrict__ Wih1, const float* __restrict__ Whh1,
    const float* __restrict__ bih1, const float* __restrict__ bhh1,
    const float* __restrict__ Wih2, const float* __restrict__ Whh2,
    const float* __restrict__ bih2, const float* __restrict__ bhh2)
{
    const int tid   = threadIdx.x;
    const int wid   = tid >> 5;
    const int lane  = tid & 31;
    const int grp   = blockIdx.x / CPG;
    const int lrank = blockIdx.x % CPG;
    const int b0    = grp * NB;
    const int u0    = lrank * 16;   // layer-1 units owned
    const int v0    = lrank * 8;    // layer-2 units owned

    unsigned* sWA1 = (unsigned*)(smem + OFF_WA1);
    unsigned* sWA2 = (unsigned*)(smem + OFF_WA2);
    float*    sAct = smem + OFF_ACT;
    float*    sR1  = smem + OFF_RED1;          // [2][64][34]
    float*    sR2  = smem + OFF_RED2;          // [4][32][34]
    float*    sb1  = smem + OFF_B1;
    float*    sb2  = smem + OFF_B2;
    float*    sc1  = smem + OFF_C1;            // [b][16]
    float*    sc2  = smem + OFF_C2;            // [b][8]

    // ================= init: weight swizzle into fragment-linear tf32 =================
    // A-frag element (mt, ks, lane l, reg r): row = mt*16 + (l>>2) + (r&1)*8,
    //                                         k   = ks*8 + (l&3) + ((r>>1)&1)*4
    for (int idx = tid; idx < 4 * NK1 * 32 * 4; idx += NTH) {
        int r = idx & 3, l = (idx >> 2) & 31, rest = idx >> 7;
        int ks = rest % NK1, mt = rest / NK1;
        int rl = mt * 16 + (l >> 2) + (r & 1) * 8;
        int k  = ks * 8 + (l & 3) + ((r >> 1) & 1) * 4;
        int gi = rl >> 4, uu = rl & 15;
        int grow = gi * H1_ + u0 + uu;
        float w = (k < F_) ? Wih1[grow * F_ + k] : Whh1[grow * H1_ + (k - F_)];
        sWA1[idx] = f2tf(w);
    }
    for (int idx = tid; idx < 2 * NK2 * 32 * 4; idx += NTH) {
        int r = idx & 3, l = (idx >> 2) & 31, rest = idx >> 7;
        int ks = rest % NK2, mt = rest / NK2;
        int rl = mt * 16 + (l >> 2) + (r & 1) * 8;
        int k  = ks * 8 + (l & 3) + ((r >> 1) & 1) * 4;
        int gi = rl >> 3, vv = rl & 7;
        int grow = gi * H2_ + v0 + vv;
        float w = (k < H1_) ? Wih2[grow * H1_ + k] : Whh2[grow * H2_ + (k - H1_)];
        sWA2[idx] = f2tf(w);
    }
    if (tid < 64) {
        int gi = tid >> 4, uu = tid & 15;
        int rr = gi * H1_ + u0 + uu;
        sb1[tid] = bih1[rr] + bhh1[rr];
    } else if (tid < 96) {
        int q = tid - 64;
        int gi = q >> 3, vv = q & 7;
        int rr = gi * H2_ + v0 + vv;
        sb2[q] = bih2[rr] + bhh2[rr];
    }
    for (int idx = tid; idx < 32 * SACT_S; idx += NTH) sAct[idx] = 0.f;
    for (int idx = tid; idx < 512; idx += NTH) sc1[idx] = 0.f;
    if (tid < 256) sc2[tid] = 0.f;
    if (tid < 256) {   // h2(-1) = 0 lives in buf[(-1)&1] = buf[1]
        int bb = tid >> 3, vv = tid & 7;
        __stcg(&g_h2[1][(b0 + bb) * H2_ + v0 + vv], 0.f);
    }
    __syncthreads();
    // stage x(0) (tf32-rounded)
    for (int idx = tid; idx < 32 * 32; idx += NTH) {
        int bb = idx >> 5, kk = idx & 31;
        u64t v = __ldg((const u64t*)(x + ((size_t)(b0 + bb) * T_) * F_) + kk);
        unsigned lo = f2tf(__uint_as_float((unsigned)v));
        unsigned hi = f2tf(__uint_as_float((unsigned)(v >> 32)));
        *(u64t*)(sAct + bb * SACT_S + 2 * kk) = ((u64t)hi << 32) | lo;
    }
    __syncthreads();

    // warp roles
    const int mt  = wid & 3, nh = (wid >> 2) & 1, kh1 = wid >> 3;   // L1: 4m x 2n x 2k
    const int mt2 = wid & 1, nh2 = (wid >> 1) & 1, kq2 = wid >> 2;  // L2: 2m x 2n x 4k
    const unsigned* actu = (const unsigned*)sAct;
    const uint4* pA1 = (const uint4*)sWA1 + mt  * NK1 * 32 + lane;
    const uint4* pA2 = (const uint4*)sWA2 + mt2 * NK2 * 32 + lane;
    const int n1a = ((2 * nh) * 8 + (lane >> 2)) * SACT_S + (lane & 3);    // L1 B rows, subtile A
    const int n1b = n1a + 8 * SACT_S;                                       // subtile B
    const int n2a = ((2 * nh2) * 8 + (lane >> 2)) * SACT_S + (lane & 3);   // L2 B rows, subtile A
    const int n2b = n2a + 8 * SACT_S;                                       // subtile B

    unsigned bseq = 0;

    for (int t = 0; t <= T_; t++) {
        // ================= MMA phase =================
        if (t < T_) {   // L1: gates(t) from x(t), h1(t-1); k-half, A shared across 2 n-subtiles
            float acc0[4] = {0,0,0,0}, acc1[4] = {0,0,0,0};
            const int kbase = kh1 * 20;
            #pragma unroll 5
            for (int j = 0; j < 20; j++) {
                uint4 A = pA1[(kbase + j) * 32];
                int kb = (kbase + j) * 8;
                int oa = n1a + kb, ob = n1b + kb;
                mma8(acc0, A, actu[oa], actu[oa + 4]);
                mma8(acc1, A, actu[ob], actu[ob + 4]);
            }
            float* R = sR1 + kh1 * 64 * SRED_S;
            int r0 = mt * 16 + (lane >> 2);
            int c0 = (2 * nh) * 8 + (lane & 3) * 2;
            *(float2*)(R + r0 * SRED_S + c0)           = make_float2(acc0[0], acc0[1]);
            *(float2*)(R + (r0 + 8) * SRED_S + c0)     = make_float2(acc0[2], acc0[3]);
            *(float2*)(R + r0 * SRED_S + c0 + 8)       = make_float2(acc1[0], acc1[1]);
            *(float2*)(R + (r0 + 8) * SRED_S + c0 + 8) = make_float2(acc1[2], acc1[3]);
        }
        if (t >= 1) {   // L2: gates for h2(t-1); k-quarter, A shared across 2 n-subtiles
            float acc0[4] = {0,0,0,0}, acc1[4] = {0,0,0,0};
            const int kbase = kq2 * 12;
            #pragma unroll 4
            for (int j = 0; j < 12; j++) {
                uint4 A = pA2[(kbase + j) * 32];
                int kb = 64 + (kbase + j) * 8;    // L2 K window starts at h1 region
                int oa = n2a + kb, ob = n2b + kb;
                mma8(acc0, A, actu[oa], actu[oa + 4]);
                mma8(acc1, A, actu[ob], actu[ob + 4]);
            }
            float* R = sR2 + kq2 * 32 * SRED_S;
            int r0 = mt2 * 16 + (lane >> 2);
            int c0 = (2 * nh2) * 8 + (lane & 3) * 2;
            *(float2*)(R + r0 * SRED_S + c0)           = make_float2(acc0[0], acc0[1]);
            *(float2*)(R + (r0 + 8) * SRED_S + c0)     = make_float2(acc0[2], acc0[3]);
            *(float2*)(R + r0 * SRED_S + c0 + 8)       = make_float2(acc1[0], acc1[1]);
            *(float2*)(R + (r0 + 8) * SRED_S + c0 + 8) = make_float2(acc1[2], acc1[3]);
        }
        __syncthreads();

        // ================= pointwise =================
        if (t < T_) {   // h1(t): 16 units x 32 batches -> g_h1[t&1]
            const int uu = tid & 15, bb = tid >> 4;
            float s0 = sR1[(0  + uu) * SRED_S + bb] + sR1[64 * SRED_S + (0  + uu) * SRED_S + bb];
            float s1 = sR1[(16 + uu) * SRED_S + bb] + sR1[64 * SRED_S + (16 + uu) * SRED_S + bb];
            float s2 = sR1[(32 + uu) * SRED_S + bb] + sR1[64 * SRED_S + (32 + uu) * SRED_S + bb];
            float s3 = sR1[(48 + uu) * SRED_S + bb] + sR1[64 * SRED_S + (48 + uu) * SRED_S + bb];
            float ii = sigm(s0 + sb1[uu]);
            float ff = sigm(s1 + sb1[16 + uu]);
            float gg = tanhfast(s2 + sb1[32 + uu]);
            float oo = sigm(s3 + sb1[48 + uu]);
            float c = sc1[bb * 16 + uu];
            c = ff * c + ii * gg;
            sc1[bb * 16 + uu] = c;
            float h = oo * tanhfast(c);
            __stcg(&g_h1[t & 1][(b0 + bb) * H1_ + u0 + uu], __uint_as_float(f2tf(h)));
        }
        if (t >= 1 && tid < 256) {   // h2(t-1): timestamp t-1 -> buf[(t-1)&1] = buf[(t+1)&1]
            const int vv = tid & 7, bb = tid >> 3;
            float s0 = 0.f, s1 = 0.f, s2 = 0.f, s3 = 0.f;
            #pragma unroll
            for (int q = 0; q < 4; q++) {
                const float* R = sR2 + q * 32 * SRED_S + bb;
                s0 += R[(0  + vv) * SRED_S];
                s1 += R[(8  + vv) * SRED_S];
                s2 += R[(16 + vv) * SRED_S];
                s3 += R[(24 + vv) * SRED_S];
            }
            float ii = sigm(s0 + sb2[vv]);
            float ff = sigm(s1 + sb2[8 + vv]);
            float gg = tanhfast(s2 + sb2[16 + vv]);
            float oo = sigm(s3 + sb2[24 + vv]);
            float c = sc2[bb * 8 + vv];
            c = ff * c + ii * gg;
            sc2[bb * 8 + vv] = c;
            float h = oo * tanhfast(c);
            __stcg(&g_h2[(t + 1) & 1][(b0 + bb) * H2_ + v0 + vv], __uint_as_float(f2tf(h)));
        }
        if (t == T_) break;

        // ---- stage x(t+1) BEFORE the barrier (overlaps global latency w/ spin) ----
        if (t + 1 < T_) {
            for (int idx = tid; idx < 32 * 32; idx += NTH) {
                int bb = idx >> 5, kk = idx & 31;
                u64t v = __ldg((const u64t*)(x + ((size_t)(b0 + bb) * T_ + (t + 1)) * F_) + kk);
                unsigned lo = f2tf(__uint_as_float((unsigned)v));
                unsigned hi = f2tf(__uint_as_float((unsigned)(v >> 32)));
                *(u64t*)(sAct + bb * SACT_S + 2 * kk) = ((u64t)hi << 32) | lo;
            }
        }

        // ================= group barrier (one per step) =================
        bseq++;
        __threadfence();
        __syncthreads();
        if (tid == 0) {
            atomicAdd(&g_cnt[grp], 1u);
            const unsigned target = (unsigned)CPG * bseq;
            while (*((volatile unsigned*)&g_cnt[grp]) < target) { }
        }
        __syncthreads();

        // ======= refresh sAct: h1(t) from buf[t&1], h2(t-1) from buf[(t+1)&1] =======
        {
            const u64t* gh1 = (const u64t*)(g_h1[t & 1] + b0 * H1_);
            for (int idx = tid; idx < 32 * 128; idx += NTH) {
                int bb = idx >> 7, kk = idx & 127;
                *(u64t*)(sAct + bb * SACT_S + 64 + 2 * kk) = __ldcg(gh1 + bb * 128 + kk);
            }
            const u64t* gh2 = (const u64t*)(g_h2[(t + 1) & 1] + b0 * H2_);
            for (int idx = tid; idx < 32 * 64; idx += NTH) {
                int bb = idx >> 6, kk = idx & 63;
                *(u64t*)(sAct + bb * SACT_S + 320 + 2 * kk) = __ldcg(gh2 + bb * 64 + kk);
            }
        }
        __syncthreads();
    }

    // ---- reset group counters for the next graph replay ----
    if (tid == 0) {
        atomicAdd(&g_done[grp], 1u);
        if (lrank == 0) {
            while (*((volatile unsigned*)&g_done[grp]) < (unsigned)CPG) { }
            g_cnt[grp] = 0;
            __threadfence();
            g_done[grp] = 0;
            __threadfence();
        }
    }
}

// ---- MLP head: out = relu(h2T @ W1^T + b1) @ W2^T + b2 ----
// final h2 timestamp = T_-1 = 999 (odd) -> buf[1]
__global__ void classify_k(const float* __restrict__ W1, const float* __restrict__ b1,
                           const float* __restrict__ W2, const float* __restrict__ b2,
                           float* __restrict__ out)
{
    __shared__ float z[DMLP_];
    const int b = blockIdx.x, d = threadIdx.x;
    const float* h = g_h2[(T_ - 1) & 1] + b * H2_;
    const float* w = W1 + d * H2_;
    float acc = b1[d];
    #pragma unroll 8
    for (int k = 0; k < H2_; k++) acc += h[k] * w[k];
    z[d] = fmaxf(acc, 0.f);
    __syncthreads();
    if (d < NCLS_) {
        const float* w2 = W2 + d * DMLP_;
        float a = b2[d];
        #pragma unroll 8
        for (int k = 0; k < DMLP_; k++) a += z[k] * w2[k];
        out[b * NCLS_ + d] = a;
    }
}

extern "C" void kernel_launch(void* const* d_in, const int* in_sizes, int n_in,
                              void* d_out, int out_size)
{
    const float* x    = (const float*)d_in[0];
    const float* Wih1 = (const float*)d_in[1];
    const float* Whh1 = (const float*)d_in[2];
    const float* bih1 = (const float*)d_in[3];
    const float* bhh1 = (const float*)d_in[4];
    const float* Wih2 = (const float*)d_in[5];
    const float* Whh2 = (const float*)d_in[6];
    const float* bih2 = (const float*)d_in[7];
    const float* bhh2 = (const float*)d_in[8];
    const float* W1   = (const float*)d_in[9];
    const float* b1   = (const float*)d_in[10];
    const float* W2   = (const float*)d_in[11];
    const float* b2   = (const float*)d_in[12];

    cudaFuncSetAttribute(lstm_persistent, cudaFuncAttributeMaxDynamicSharedMemorySize, SMEM_BYTES);

    lstm_persistent<<<NG * CPG, NTH, SMEM_BYTES>>>(x, Wih1, Whh1, bih1, bhh1,
                                                   Wih2, Whh2, bih2, bhh2);
    classify_k<<<B_, DMLP_>>>(W1, b1, W2, b2, (float*)d_out);
}

// round 16
// speedup vs baseline: 1.0386x; 1.0386x over previous
#include <cuda_runtime.h>
#include <cuda_bf16.h>
#include <cstdint>

// Problem dims
#define B_    256
#define T_    1000
#define F_    64
#define H1_   256
#define H2_   128
#define NCLS_ 5
#define DMLP_ 128

// Persistent-kernel config: 8 groups x 16 CTAs = 128 CTAs co-resident
#define NG    8
#define CPG   16
#define NB    32
#define NTH   512

// MMA tiling
#define NK1   40          // L1 k-steps (K=320, 8 per step)
#define NK2   48          // L2 k-steps (K=384)

// SMEM layout (float offsets)
#define SACT_S   452      // [batch][x(64) | h1(256) | h2(128)] stride, ≡4 mod 32
#define SRED_S   34
#define OFF_WA1  0                        // 4*NK1*32*4  = 20480
#define OFF_WA2  (OFF_WA1 + 20480)        // 2*NK2*32*4  = 12288
#define OFF_ACT  (OFF_WA2 + 12288)        // 32*452      = 14464
#define OFF_RED1 (OFF_ACT + 14464)        // 2 copies *64*34 = 4352
#define OFF_RED2 (OFF_RED1 + 4352)        // 4 copies *32*34 = 4352
#define OFF_B1   (OFF_RED2 + 4352)        // 64
#define OFF_B2   (OFF_B1 + 64)            // 32
#define OFF_C1   (OFF_B2 + 32)            // 512
#define OFF_C2   (OFF_C1 + 512)           // 256
#define SMEM_FLOATS (OFF_C2 + 256)
#define SMEM_BYTES  (SMEM_FLOATS * 4)     // 227200 B

typedef unsigned long long u64t;

// Ping-pong state buffers: h(s) lives in buf[s&1].
__device__ float    g_h1[2][B_ * H1_];
__device__ float    g_h2[2][B_ * H2_];
// Split-phase flags: flagA[r]=s  <=> h1(s-1) stored by CTA r.
//                    flagB[r]=s  <=> h2(s-1) stored by CTA r.
__device__ unsigned g_flagA[NG][CPG];
__device__ unsigned g_flagB[NG][CPG];
__device__ unsigned g_done[NG];

__device__ __forceinline__ unsigned f2tf(float f) {
    unsigned u;
    asm("cvt.rna.tf32.f32 %0, %1;" : "=r"(u) : "f"(f));
    return u;
}
__device__ __forceinline__ void mma8(float* d, uint4 a, unsigned b0, unsigned b1) {
    asm("mma.sync.aligned.m16n8k8.row.col.f32.tf32.tf32.f32 "
        "{%0,%1,%2,%3},{%4,%5,%6,%7},{%8,%9},{%0,%1,%2,%3};"
        : "+f"(d[0]), "+f"(d[1]), "+f"(d[2]), "+f"(d[3])
        : "r"(a.x), "r"(a.y), "r"(a.z), "r"(a.w), "r"(b0), "r"(b1));
}
__device__ __forceinline__ float tanhfast(float x) {
    float y;
    asm("tanh.approx.f32 %0, %1;" : "=f"(y) : "f"(x));
    return y;
}
__device__ __forceinline__ float sigm(float x)  { return 0.5f * tanhfast(0.5f * x) + 0.5f; }

__device__ __forceinline__ unsigned ld_acq(const unsigned* p) {
    unsigned v;
    asm volatile("ld.acquire.gpu.u32 %0, [%1];" : "=r"(v) : "l"(p) : "memory");
    return v;
}
__device__ __forceinline__ void st_rel(unsigned* p, unsigned v) {
    asm volatile("st.release.gpu.u32 [%0], %1;" :: "l"(p), "r"(v) : "memory");
}

extern __shared__ float smem[];

__global__ void __launch_bounds__(NTH, 1) lstm_persistent(
    const float* __restrict__ x,
    const float* __restrict__ Wih1, const float* __restrict__ Whh1,
    const float* __restrict__ bih1, const float* __restrict__ bhh1,
    const float* __restrict__ Wih2, const float* __restrict__ Whh2,
    const float* __restrict__ bih2, const float* __restrict__ bhh2)
{
    const int tid   = threadIdx.x;
    const int wid   = tid >> 5;
    const int lane  = tid & 31;
    const int grp   = blockIdx.x / CPG;
    const int lrank = blockIdx.x % CPG;
    const int b0    = grp * NB;
    const int u0    = lrank * 16;   // layer-1 units owned
    const int v0    = lrank * 8;    // layer-2 units owned

    unsigned* sWA1 = (unsigned*)(smem + OFF_WA1);
    unsigned* sWA2 = (unsigned*)(smem + OFF_WA2);
    float*    sAct = smem + OFF_ACT;
    float*    sR1  = smem + OFF_RED1;          // [2][64][34]
    float*    sR2  = smem + OFF_RED2;          // [4][32][34]
    float*    sb1  = smem + OFF_B1;
    float*    sb2  = smem + OFF_B2;
    float*    sc1  = smem + OFF_C1;            // [b][16]
    float*    sc2  = smem + OFF_C2;            // [b][8]

    // ================= init: weight swizzle into fragment-linear tf32 =================
    for (int idx = tid; idx < 4 * NK1 * 32 * 4; idx += NTH) {
        int r = idx & 3, l = (idx >> 2) & 31, rest = idx >> 7;
        int ks = rest % NK1, mt = rest / NK1;
        int rl = mt * 16 + (l >> 2) + (r & 1) * 8;
        int k  = ks * 8 + (l & 3) + ((r >> 1) & 1) * 4;
        int gi = rl >> 4, uu = rl & 15;
        int grow = gi * H1_ + u0 + uu;
        float w = (k < F_) ? Wih1[grow * F_ + k] : Whh1[grow * H1_ + (k - F_)];
        sWA1[idx] = f2tf(w);
    }
    for (int idx = tid; idx < 2 * NK2 * 32 * 4; idx += NTH) {
        int r = idx & 3, l = (idx >> 2) & 31, rest = idx >> 7;
        int ks = rest % NK2, mt = rest / NK2;
        int rl = mt * 16 + (l >> 2) + (r & 1) * 8;
        int k  = ks * 8 + (l & 3) + ((r >> 1) & 1) * 4;
        int gi = rl >> 3, vv = rl & 7;
        int grow = gi * H2_ + v0 + vv;
        float w = (k < H1_) ? Wih2[grow * H1_ + k] : Whh2[grow * H2_ + (k - H1_)];
        sWA2[idx] = f2tf(w);
    }
    if (tid < 64) {
        int gi = tid >> 4, uu = tid & 15;
        int rr = gi * H1_ + u0 + uu;
        sb1[tid] = bih1[rr] + bhh1[rr];
    } else if (tid < 96) {
        int q = tid - 64;
        int gi = q >> 3, vv = q & 7;
        int rr = gi * H2_ + v0 + vv;
        sb2[q] = bih2[rr] + bhh2[rr];
    }
    for (int idx = tid; idx < 32 * SACT_S; idx += NTH) sAct[idx] = 0.f;
    for (int idx = tid; idx < 512; idx += NTH) sc1[idx] = 0.f;
    if (tid < 256) sc2[tid] = 0.f;
    if (tid < 256) {   // h2(-1) = 0 lives in buf[(-1)&1] = buf[1]
        int bb = tid >> 3, vv = tid & 7;
        __stcg(&g_h2[1][(b0 + bb) * H2_ + v0 + vv], 0.f);
    }
    __syncthreads();
    // stage x(0) (tf32-rounded)
    for (int idx = tid; idx < 32 * 32; idx += NTH) {
        int bb = idx >> 5, kk = idx & 31;
        u64t v = __ldg((const u64t*)(x + ((size_t)(b0 + bb) * T_) * F_) + kk);
        unsigned lo = f2tf(__uint_as_float((unsigned)v));
        unsigned hi = f2tf(__uint_as_float((unsigned)(v >> 32)));
        *(u64t*)(sAct + bb * SACT_S + 2 * kk) = ((u64t)hi << 32) | lo;
    }
    __syncthreads();

    // warp roles
    const int mt  = wid & 3, nh = (wid >> 2) & 1, kh1 = wid >> 3;   // L1: 4m x 2n x 2k
    const int mt2 = wid & 1, nh2 = (wid >> 1) & 1, kq2 = wid >> 2;  // L2: 2m x 2n x 4k
    const unsigned* actu = (const unsigned*)sAct;
    const uint4* pA1 = (const uint4*)sWA1 + mt  * NK1 * 32 + lane;
    const uint4* pA2 = (const uint4*)sWA2 + mt2 * NK2 * 32 + lane;
    const int n1a = ((2 * nh) * 8 + (lane >> 2)) * SACT_S + (lane & 3);
    const int n1b = n1a + 8 * SACT_S;
    const int n2a = ((2 * nh2) * 8 + (lane >> 2)) * SACT_S + (lane & 3);
    const int n2b = n2a + 8 * SACT_S;

    for (int t = 0; t <= T_; t++) {
        // ================= A: L1 MMA(t) [reads x(t), h1(t-1)] =================
        if (t < T_) {
            float acc0[4] = {0,0,0,0}, acc1[4] = {0,0,0,0};
            const int kbase = kh1 * 20;
            #pragma unroll 5
            for (int j = 0; j < 20; j++) {
                uint4 A = pA1[(kbase + j) * 32];
                int kb = (kbase + j) * 8;
                int oa = n1a + kb, ob = n1b + kb;
                mma8(acc0, A, actu[oa], actu[oa + 4]);
                mma8(acc1, A, actu[ob], actu[ob + 4]);
            }
            float* R = sR1 + kh1 * 64 * SRED_S;
            int r0 = mt * 16 + (lane >> 2);
            int c0 = (2 * nh) * 8 + (lane & 3) * 2;
            *(float2*)(R + r0 * SRED_S + c0)           = make_float2(acc0[0], acc0[1]);
            *(float2*)(R + (r0 + 8) * SRED_S + c0)     = make_float2(acc0[2], acc0[3]);
            *(float2*)(R + r0 * SRED_S + c0 + 8)       = make_float2(acc1[0], acc1[1]);
            *(float2*)(R + (r0 + 8) * SRED_S + c0 + 8) = make_float2(acc1[2], acc1[3]);
        }
        __syncthreads();   // sR1 ready

        // ====== B: deferred h2 wait + refresh, h1(t) pointwise, x(t+1) stage ======
        if (t >= 1) {
            // wait for h2(t-2) (posted by all CTAs at D(t-1) — a full half-step ago)
            const unsigned need = (unsigned)(t - 1);
            bool ok;
            do {
                unsigned v = (lane < CPG) ? ld_acq(&g_flagB[grp][lane]) : 0xffffffffu;
                ok = __all_sync(0xffffffffu, v >= need);
            } while (!ok);
            const u64t* gh2 = (const u64t*)(g_h2[t & 1] + b0 * H2_);   // h2(t-2) in buf[(t-2)&1]
            for (int idx = tid; idx < 32 * 64; idx += NTH) {
                int bb = idx >> 6, kk = idx & 63;
                *(u64t*)(sAct + bb * SACT_S + 320 + 2 * kk) = __ldcg(gh2 + bb * 64 + kk);
            }
        }
        if (t < T_) {   // h1(t): 16 units x 32 batches -> g_h1[t&1]
            const int uu = tid & 15, bb = tid >> 4;
            float s0 = sR1[(0  + uu) * SRED_S + bb] + sR1[64 * SRED_S + (0  + uu) * SRED_S + bb];
            float s1 = sR1[(16 + uu) * SRED_S + bb] + sR1[64 * SRED_S + (16 + uu) * SRED_S + bb];
            float s2 = sR1[(32 + uu) * SRED_S + bb] + sR1[64 * SRED_S + (32 + uu) * SRED_S + bb];
            float s3 = sR1[(48 + uu) * SRED_S + bb] + sR1[64 * SRED_S + (48 + uu) * SRED_S + bb];
            float ii = sigm(s0 + sb1[uu]);
            float ff = sigm(s1 + sb1[16 + uu]);
            float gg = tanhfast(s2 + sb1[32 + uu]);
            float oo = sigm(s3 + sb1[48 + uu]);
            float c = sc1[bb * 16 + uu];
            c = ff * c + ii * gg;
            sc1[bb * 16 + uu] = c;
            float h = oo * tanhfast(c);
            __stcg(&g_h1[t & 1][(b0 + bb) * H1_ + u0 + uu], __uint_as_float(f2tf(h)));
        }
        if (t + 1 < T_) {   // stage x(t+1)
            for (int idx = tid; idx < 32 * 32; idx += NTH) {
                int bb = idx >> 5, kk = idx & 31;
                u64t v = __ldg((const u64t*)(x + ((size_t)(b0 + bb) * T_ + (t + 1)) * F_) + kk);
                unsigned lo = f2tf(__uint_as_float((unsigned)v));
                unsigned hi = f2tf(__uint_as_float((unsigned)(v >> 32)));
                *(u64t*)(sAct + bb * SACT_S + 2 * kk) = ((u64t)hi << 32) | lo;
            }
        }
        __syncthreads();   // h1 stores, h2 refresh, x stage complete
        if (t < T_ && tid == 0) st_rel(&g_flagA[grp][lrank], (unsigned)(t + 1));  // early release of h1(t)

        // ================= C: L2 MMA(t-1) [reads h1(t-1), h2(t-2)] =================
        if (t >= 1) {
            float acc0[4] = {0,0,0,0}, acc1[4] = {0,0,0,0};
            const int kbase = kq2 * 12;
            #pragma unroll 4
            for (int j = 0; j < 12; j++) {
                uint4 A = pA2[(kbase + j) * 32];
                int kb = 64 + (kbase + j) * 8;
                int oa = n2a + kb, ob = n2b + kb;
                mma8(acc0, A, actu[oa], actu[oa + 4]);
                mma8(acc1, A, actu[ob], actu[ob + 4]);
            }
            float* R = sR2 + kq2 * 32 * SRED_S;
            int r0 = mt2 * 16 + (lane >> 2);
            int c0 = (2 * nh2) * 8 + (lane & 3) * 2;
            *(float2*)(R + r0 * SRED_S + c0)           = make_float2(acc0[0], acc0[1]);
            *(float2*)(R + (r0 + 8) * SRED_S + c0)     = make_float2(acc0[2], acc0[3]);
            *(float2*)(R + r0 * SRED_S + c0 + 8)       = make_float2(acc1[0], acc1[1]);
            *(float2*)(R + (r0 + 8) * SRED_S + c0 + 8) = make_float2(acc1[2], acc1[3]);
        }
        __syncthreads();   // sR2 ready

        // ================= D: h2(t-1) pointwise =================
        if (t >= 1 && tid < 256) {
            const int vv = tid & 7, bb = tid >> 3;
            float s0 = 0.f, s1 = 0.f, s2 = 0.f, s3 = 0.f;
            #pragma unroll
            for (int q = 0; q < 4; q++) {
                const float* R = sR2 + q * 32 * SRED_S + bb;
                s0 += R[(0  + vv) * SRED_S];
                s1 += R[(8  + vv) * SRED_S];
                s2 += R[(16 + vv) * SRED_S];
                s3 += R[(24 + vv) * SRED_S];
            }
            float ii = sigm(s0 + sb2[vv]);
            float ff = sigm(s1 + sb2[8 + vv]);
            float gg = tanhfast(s2 + sb2[16 + vv]);
            float oo = sigm(s3 + sb2[24 + vv]);
            float c = sc2[bb * 8 + vv];
            c = ff * c + ii * gg;
            sc2[bb * 8 + vv] = c;
            float h = oo * tanhfast(c);
            __stcg(&g_h2[(t + 1) & 1][(b0 + bb) * H2_ + v0 + vv], __uint_as_float(f2tf(h)));
        }
        __syncthreads();   // h2 stores complete
        if (t >= 1 && tid == 0) st_rel(&g_flagB[grp][lrank], (unsigned)t);

        if (t == T_) break;

        // ===== E: wait h1(t) (released half a step ago by all CTAs) + refresh =====
        {
            const unsigned need = (unsigned)(t + 1);
            bool ok;
            do {
                unsigned v = (lane < CPG) ? ld_acq(&g_flagA[grp][lane]) : 0xffffffffu;
                ok = __all_sync(0xffffffffu, v >= need);
            } while (!ok);
            const u64t* gh1 = (const u64t*)(g_h1[t & 1] + b0 * H1_);
            for (int idx = tid; idx < 32 * 128; idx += NTH) {
                int bb = idx >> 7, kk = idx & 127;
                *(u64t*)(sAct + bb * SACT_S + 64 + 2 * kk) = __ldcg(gh1 + bb * 128 + kk);
            }
        }
        __syncthreads();   // sAct.h1 ready for A(t+1)
    }

    // ---- reset flags for the next graph replay ----
    if (tid == 0) {
        atomicAdd(&g_done[grp], 1u);
        if (lrank == 0) {
            while (*((volatile unsigned*)&g_done[grp]) < (unsigned)CPG) { }
            for (int i = 0; i < CPG; i++) { g_flagA[grp][i] = 0; g_flagB[grp][i] = 0; }
            __threadfence();
            g_done[grp] = 0;
            __threadfence();
        }
    }
}

// ---- MLP head: out = relu(h2T @ W1^T + b1) @ W2^T + b2 ----
// final h2 timestamp = T_-1 = 999 (odd) -> buf[1]
__global__ void classify_k(const float* __restrict__ W1, const float* __restrict__ b1,
                           const float* __restrict__ W2, const float* __restrict__ b2,
                           float* __restrict__ out)
{
    __shared__ float z[DMLP_];
    const int b = blockIdx.x, d = threadIdx.x;
    const float* h = g_h2[(T_ - 1) & 1] + b * H2_;
    const float* w = W1 + d * H2_;
    float acc = b1[d];
    #pragma unroll 8
    for (int k = 0; k < H2_; k++) acc += h[k] * w[k];
    z[d] = fmaxf(acc, 0.f);
    __syncthreads();
    if (d < NCLS_) {
        const float* w2 = W2 + d * DMLP_;
        float a = b2[d];
        #pragma unroll 8
        for (int k = 0; k < DMLP_; k++) a += z[k] * w2[k];
        out[b * NCLS_ + d] = a;
    }
}

extern "C" void kernel_launch(void* const* d_in, const int* in_sizes, int n_in,
                              void* d_out, int out_size)
{
    const float* x    = (const float*)d_in[0];
    const float* Wih1 = (const float*)d_in[1];
    const float* Whh1 = (const float*)d_in[2];
    const float* bih1 = (const float*)d_in[3];
    const float* bhh1 = (const float*)d_in[4];
    const float* Wih2 = (const float*)d_in[5];
    const float* Whh2 = (const float*)d_in[6];
    const float* bih2 = (const float*)d_in[7];
    const float* bhh2 = (const float*)d_in[8];
    const float* W1   = (const float*)d_in[9];
    const float* b1   = (const float*)d_in[10];
    const float* W2   = (const float*)d_in[11];
    const float* b2   = (const float*)d_in[12];

    cudaFuncSetAttribute(lstm_persistent, cudaFuncAttributeMaxDynamicSharedMemorySize, SMEM_BYTES);

    lstm_persistent<<<NG * CPG, NTH, SMEM_BYTES>>>(x, Wih1, Whh1, bih1, bhh1,
                                                   Wih2, Whh2, bih2, bhh2);
    classify_k<<<B_, DMLP_>>>(W1, b1, W2, b2, (float*)d_out);
}